// round 1
// baseline (speedup 1.0000x reference)
#include <cuda_runtime.h>

#define NB 8
#define TT 20
#define CIN 32
#define COUT 64
#define HH 64
#define WW 64
#define OHH 32
#define OWW 32
#define KTOT (CIN*9)        /* 288 */
#define NIMG_SPK (NB*TT)    /* 160 */
#define NIMG (NIMG_SPK+NB)  /* 168 */
#define KC 8
#define NKC (KTOT/KC)       /* 36 */

#define COUNT_OFF (NB*TT*COUT*OHH*OWW)            /* 10485760 */
#define ANN_OFF   (COUNT_OFF + NB*COUT*OHH*OWW)   /* 11010048 */

// Scratch (allocation-free rule: __device__ globals)
__device__ float g_wT[2][KTOT][COUT];          // transposed folded weights [set][k][co]
__device__ float g_bias[2][COUT];              // folded bias
__device__ float g_pooled[TT][NB][COUT][OHH*OWW];  // 42 MB pooled pre-spike potentials

// ---------------------------------------------------------------------------
// Fold BN into conv weights/bias. set 0: spiking path ratio = gamma/sqrt(rv)
// (NO eps, matching source). set 1: ANN path scale = gamma/sqrt(rv+1e-5).
// ---------------------------------------------------------------------------
__global__ void prep_kernel(const float* __restrict__ w, const float* __restrict__ b,
                            const float* __restrict__ gamma, const float* __restrict__ beta,
                            const float* __restrict__ rm, const float* __restrict__ rv)
{
    int idx = blockIdx.x * blockDim.x + threadIdx.x;
    if (idx < 2 * KTOT * COUT) {
        int set = idx / (KTOT * COUT);
        int rem = idx - set * (KTOT * COUT);
        int k  = rem / COUT;
        int co = rem - k * COUT;
        float ratio = gamma[co] / sqrtf(set ? rv[co] + 1e-5f : rv[co]);
        g_wT[set][k][co] = w[co * KTOT + k] * ratio;
    }
    if (idx < 2 * COUT) {
        int set = idx / COUT;
        int co  = idx - set * COUT;
        float ratio = gamma[co] / sqrtf(set ? rv[co] + 1e-5f : rv[co]);
        g_bias[set][co] = (b[co] - rm[co]) * ratio + beta[co];
    }
}

// ---------------------------------------------------------------------------
// Fused conv(3x3, pad 1) + bias + 2x2 maxpool (+ReLU for ANN images).
// Implicit GEMM: M=128 pixels (2 consecutive image rows), N=64 couts, K=288.
// grid = (168 images, 32 pooled rows). 256 threads, thread tile 4 pix x 8 co
// where the 4 pixels are exactly one 2x2 pool window -> pooling is local.
// ---------------------------------------------------------------------------
__global__ __launch_bounds__(256, 3)
void conv_pool_kernel(const float* __restrict__ x_st, const float* __restrict__ x_sc,
                      float* __restrict__ out)
{
    __shared__ __align__(16) float sA[2][KC][128];
    __shared__ __align__(16) float sB[2][KC][COUT];

    const int img = blockIdx.x;
    const int pr  = blockIdx.y;            // pooled output row 0..31
    const int tid = threadIdx.x;
    const int tm  = tid & 31;              // pooled col
    const int tn  = tid >> 5;              // cout group (8 co each)
    const int set = (img >= NIMG_SPK) ? 1 : 0;

    const float* inbase = set ? (x_sc + (size_t)(img - NIMG_SPK) * CIN * HH * WW)
                              : (x_st + (size_t)img * CIN * HH * WW);
    const float* wTp = &g_wT[set][0][0];

    // A-tile gather indices: 1024 elems = 8 k-rows x 128 pix, 4 per thread
    const int kkA  = tid >> 5;             // k row within chunk
    const int mA   = (tid & 31) << 2;      // first pixel index (4 consecutive)
    const int rowA = 2 * pr + (mA >> 6);   // image row for these pixels
    const int colA = mA & 63;
    // B-tile indices: 512 elems = 8 k-rows x 64 co, 2 per thread
    const int kkB = tid >> 6;              // 0..3 (also +4)
    const int coB = tid & 63;

    float acc0[8], acc1[8], acc2[8], acc3[8];
#pragma unroll
    for (int j = 0; j < 8; j++) { acc0[j]=0.f; acc1[j]=0.f; acc2[j]=0.f; acc3[j]=0.f; }

    // ---- prologue: chunk 0 -> smem buffer 0 ----
    {
        int k = kkA;
        int cin = k / 9; int r9 = k - cin * 9; int ky = r9 / 3; int kx = r9 - ky * 3;
        int iy = rowA + ky - 1;
        const float* src = inbase + (cin * HH + iy) * WW;
        bool vy = ((unsigned)iy < HH);
        float v[4];
#pragma unroll
        for (int j = 0; j < 4; j++) {
            int ix = colA + kx - 1 + j;
            v[j] = (vy && (unsigned)ix < WW) ? src[ix] : 0.f;
        }
        *(float4*)&sA[0][kkA][mA] = make_float4(v[0], v[1], v[2], v[3]);
        sB[0][kkB][coB]     = wTp[kkB * COUT + coB];
        sB[0][kkB + 4][coB] = wTp[(kkB + 4) * COUT + coB];
    }
    __syncthreads();

    float ra[4], rb[2];
    for (int c = 0; c < NKC; c++) {
        const int cur = c & 1;
        const bool has_next = (c + 1 < NKC);
        if (has_next) {
            int k0 = (c + 1) * KC;
            int k = k0 + kkA;
            int cin = k / 9; int r9 = k - cin * 9; int ky = r9 / 3; int kx = r9 - ky * 3;
            int iy = rowA + ky - 1;
            const float* src = inbase + (cin * HH + iy) * WW;
            bool vy = ((unsigned)iy < HH);
#pragma unroll
            for (int j = 0; j < 4; j++) {
                int ix = colA + kx - 1 + j;
                ra[j] = (vy && (unsigned)ix < WW) ? src[ix] : 0.f;
            }
            rb[0] = wTp[(k0 + kkB) * COUT + coB];
            rb[1] = wTp[(k0 + kkB + 4) * COUT + coB];
        }
#pragma unroll
        for (int kk = 0; kk < KC; kk++) {
            float2 a01 = *(const float2*)&sA[cur][kk][2 * tm];
            float2 a23 = *(const float2*)&sA[cur][kk][64 + 2 * tm];
            float4 b0  = *(const float4*)&sB[cur][kk][8 * tn];
            float4 b1  = *(const float4*)&sB[cur][kk][8 * tn + 4];
            float bv[8] = { b0.x, b0.y, b0.z, b0.w, b1.x, b1.y, b1.z, b1.w };
#pragma unroll
            for (int j = 0; j < 8; j++) {
                acc0[j] = fmaf(a01.x, bv[j], acc0[j]);
                acc1[j] = fmaf(a01.y, bv[j], acc1[j]);
                acc2[j] = fmaf(a23.x, bv[j], acc2[j]);
                acc3[j] = fmaf(a23.y, bv[j], acc3[j]);
            }
        }
        if (has_next) {
            int nb_ = cur ^ 1;
            *(float4*)&sA[nb_][kkA][mA] = make_float4(ra[0], ra[1], ra[2], ra[3]);
            sB[nb_][kkB][coB]     = rb[0];
            sB[nb_][kkB + 4][coB] = rb[1];
            __syncthreads();
        }
    }

    // ---- epilogue: bias + 2x2 maxpool (+ReLU/store split per path) ----
    const float* bias = g_bias[set];
    if (!set) {
        int n = img / TT, t = img - n * TT;
        float* dst = &g_pooled[t][n][0][pr * OWW + tm];
#pragma unroll
        for (int j = 0; j < 8; j++) {
            int co = 8 * tn + j;
            float v = fmaxf(fmaxf(acc0[j], acc1[j]), fmaxf(acc2[j], acc3[j])) + bias[co];
            dst[(size_t)co * (OHH * OWW)] = v;
        }
    } else {
        int n = img - NIMG_SPK;
        float* dst = out + ANN_OFF + ((size_t)n * COUT * OHH + pr) * OWW + tm;
#pragma unroll
        for (int j = 0; j < 8; j++) {
            int co = 8 * tn + j;
            float v = fmaxf(fmaxf(acc0[j], acc1[j]), fmaxf(acc2[j], acc3[j])) + bias[co];
            dst[(size_t)co * (OHH * OWW)] = fmaxf(v, 0.f);
        }
    }
}

// ---------------------------------------------------------------------------
// Temporal LIF scan: each thread owns one (n, c, pixel) neuron, loops T=20.
// spike = (pot >= 1) * (1 - mask); pot -= spike; mask latches at 1.
// Writes spike_out [N,T,C,32,32] and spike_count [N,C,32,32].
// ---------------------------------------------------------------------------
__global__ void scan_kernel(float* __restrict__ out)
{
    int idx = blockIdx.x * blockDim.x + threadIdx.x;
    if (idx >= NB * COUT * OHH * OWW) return;
    int pix = idx & 1023;
    int c   = (idx >> 10) & 63;
    int n   = idx >> 16;

    const float* src = &g_pooled[0][n][c][pix];
    float* dspike = out + (((size_t)n * TT) * COUT + c) * 1024 + pix;

    float pot = 0.f, mask = 0.f, cnt = 0.f;
#pragma unroll
    for (int t = 0; t < TT; t++) {
        pot += src[(size_t)t * NB * COUT * 1024];
        float s = (pot >= 1.f) ? (1.f - mask) : 0.f;
        pot -= s;
        if (s != 0.f) mask = 1.f;
        cnt += s;
        dspike[(size_t)t * COUT * 1024] = s;
    }
    out[COUNT_OFF + (size_t)idx] = cnt;
}

// ---------------------------------------------------------------------------
extern "C" void kernel_launch(void* const* d_in, const int* in_sizes, int n_in,
                              void* d_out, int out_size)
{
    const float* x_st  = (const float*)d_in[0];  // (8,20,32,64,64)
    const float* x_sc  = (const float*)d_in[1];  // (8,32,64,64)
    const float* w     = (const float*)d_in[2];  // (64,32,3,3)
    const float* b     = (const float*)d_in[3];  // (64)
    const float* gamma = (const float*)d_in[4];
    const float* beta  = (const float*)d_in[5];
    const float* rm    = (const float*)d_in[6];
    const float* rv    = (const float*)d_in[7];
    float* out = (float*)d_out;
    (void)in_sizes; (void)n_in; (void)out_size;

    prep_kernel<<<(2 * KTOT * COUT + 255) / 256, 256>>>(w, b, gamma, beta, rm, rv);
    conv_pool_kernel<<<dim3(NIMG, OHH), 256>>>(x_st, x_sc, out);
    scan_kernel<<<(NB * COUT * OHH * OWW + 255) / 256, 256>>>(out);
}

// round 3
// speedup vs baseline: 1.0885x; 1.0885x over previous
#include <cuda_runtime.h>

#define NB 8
#define TT 20
#define CIN 32
#define COUT 64
#define HH 64
#define WW 64
#define OHH 32
#define OWW 32
#define KTOT (CIN*9)        /* 288 */
#define NIMG_SPK (NB*TT)    /* 160 */
#define NIMG (NIMG_SPK+NB)  /* 168 */
#define KC 8
#define NKC (KTOT/KC)       /* 36 */

#define COUNT_OFF (NB*TT*COUT*OHH*OWW)            /* 10485760 */
#define ANN_OFF   (COUNT_OFF + NB*COUT*OHH*OWW)   /* 11010048 */

// Scratch (allocation-free rule: __device__ globals)
__device__ float g_wT[2][KTOT][COUT];          // transposed folded weights [set][k][co]
__device__ float g_bias[2][COUT];              // folded bias
__device__ float g_pooled[TT][NB][COUT][OHH*OWW];  // 42 MB pooled pre-spike potentials

typedef unsigned long long u64;

// Packed fp32x2 FMA (Blackwell-only; ptxas never emits this from C++).
__device__ __forceinline__ void fma2(u64& d, u64 a, u64 b) {
    asm("fma.rn.f32x2 %0, %1, %2, %0;" : "+l"(d) : "l"(a), "l"(b));
}
// Duplicate one fp32 into both halves of a packed f32x2.
__device__ __forceinline__ u64 dup2(float x) {
    u64 d; unsigned u = __float_as_uint(x);
    asm("mov.b64 %0, {%1, %1};" : "=l"(d) : "r"(u));
    return d;
}
__device__ __forceinline__ void unpack2(u64 v, float& lo, float& hi) {
    unsigned a, b;
    asm("mov.b64 {%0, %1}, %2;" : "=r"(a), "=r"(b) : "l"(v));
    lo = __uint_as_float(a); hi = __uint_as_float(b);
}

// ---------------------------------------------------------------------------
// Fold BN into conv weights/bias. set 0: spiking path ratio = gamma/sqrt(rv)
// (NO eps, matching source). set 1: ANN path scale = gamma/sqrt(rv+1e-5).
// ---------------------------------------------------------------------------
__global__ void prep_kernel(const float* __restrict__ w, const float* __restrict__ b,
                            const float* __restrict__ gamma, const float* __restrict__ beta,
                            const float* __restrict__ rm, const float* __restrict__ rv)
{
    int idx = blockIdx.x * blockDim.x + threadIdx.x;
    if (idx < 2 * KTOT * COUT) {
        int set = idx / (KTOT * COUT);
        int rem = idx - set * (KTOT * COUT);
        int k  = rem / COUT;
        int co = rem - k * COUT;
        float ratio = gamma[co] / sqrtf(set ? rv[co] + 1e-5f : rv[co]);
        g_wT[set][k][co] = w[co * KTOT + k] * ratio;
    }
    if (idx < 2 * COUT) {
        int set = idx / COUT;
        int co  = idx - set * COUT;
        float ratio = gamma[co] / sqrtf(set ? rv[co] + 1e-5f : rv[co]);
        g_bias[set][co] = (b[co] - rm[co]) * ratio + beta[co];
    }
}

// ---------------------------------------------------------------------------
// Fused conv(3x3, pad 1) + bias + 2x2 maxpool (+ReLU for ANN images).
// Implicit GEMM: M=128 pixels (2 image rows), N=64 couts, K=288, KC=8 chunks,
// double-buffered smem. Thread tile 4 pix x 8 co held as 4x4 packed f32x2
// accumulators; inner loop is 16 FFMA2 per kk (2 FMAs per issue slot).
// ---------------------------------------------------------------------------
__global__ __launch_bounds__(256, 3)
void conv_pool_kernel(const float* __restrict__ x_st, const float* __restrict__ x_sc,
                      float* __restrict__ out)
{
    __shared__ __align__(16) float sA[2][KC][128];
    __shared__ __align__(16) float sB[2][KC][COUT];

    const int img = blockIdx.x;
    const int pr  = blockIdx.y;            // pooled output row 0..31
    const int tid = threadIdx.x;
    const int tm  = tid & 31;              // pooled col
    const int tn  = tid >> 5;              // cout group (8 co each)
    const int set = (img >= NIMG_SPK) ? 1 : 0;

    const float* inbase = set ? (x_sc + (size_t)(img - NIMG_SPK) * CIN * HH * WW)
                              : (x_st + (size_t)img * CIN * HH * WW);
    const float* wTp = &g_wT[set][0][0];

    // A-tile gather: 1024 elems = 8 k-rows x 128 pix, 4 consecutive pix/thread
    const int kkA  = tid >> 5;
    const int mA   = (tid & 31) << 2;
    const int rowA = 2 * pr + (mA >> 6);
    const int colA = mA & 63;
    // B-tile gather: 512 elems = 8 k-rows x 64 co, 2 per thread
    const int kkB = tid >> 6;
    const int coB = tid & 63;

    u64 acc[4][4];                          // [pixel][co-pair]
#pragma unroll
    for (int p = 0; p < 4; p++)
#pragma unroll
        for (int c = 0; c < 4; c++) acc[p][c] = 0ull;

    // ---- prologue: chunk 0 -> smem buffer 0 ----
    {
        int k = kkA;
        int cin = k / 9; int r9 = k - cin * 9; int ky = r9 / 3; int kx = r9 - ky * 3;
        int iy = rowA + ky - 1;
        const float* src = inbase + (cin * HH + iy) * WW;
        bool vy = ((unsigned)iy < HH);
        float v[4];
#pragma unroll
        for (int j = 0; j < 4; j++) {
            int ix = colA + kx - 1 + j;
            v[j] = (vy && (unsigned)ix < WW) ? src[ix] : 0.f;
        }
        *(float4*)&sA[0][kkA][mA] = make_float4(v[0], v[1], v[2], v[3]);
        sB[0][kkB][coB]     = wTp[kkB * COUT + coB];
        sB[0][kkB + 4][coB] = wTp[(kkB + 4) * COUT + coB];
    }
    __syncthreads();

    float ra[4], rb[2];
    for (int c = 0; c < NKC; c++) {
        const int cur = c & 1;
        const bool has_next = (c + 1 < NKC);
        if (has_next) {
            int k0 = (c + 1) * KC;
            int k = k0 + kkA;
            int cin = k / 9; int r9 = k - cin * 9; int ky = r9 / 3; int kx = r9 - ky * 3;
            int iy = rowA + ky - 1;
            const float* src = inbase + (cin * HH + iy) * WW;
            bool vy = ((unsigned)iy < HH);
#pragma unroll
            for (int j = 0; j < 4; j++) {
                int ix = colA + kx - 1 + j;
                ra[j] = (vy && (unsigned)ix < WW) ? src[ix] : 0.f;
            }
            rb[0] = wTp[(k0 + kkB) * COUT + coB];
            rb[1] = wTp[(k0 + kkB + 4) * COUT + coB];
        }
#pragma unroll
        for (int kk = 0; kk < KC; kk++) {
            float2 a01 = *(const float2*)&sA[cur][kk][2 * tm];
            float2 a23 = *(const float2*)&sA[cur][kk][64 + 2 * tm];
            // co-pairs: LDS.128 of 4 consecutive couts == 2 packed f32x2 regs
            ulonglong2 b0 = *(const ulonglong2*)&sB[cur][kk][8 * tn];
            ulonglong2 b1 = *(const ulonglong2*)&sB[cur][kk][8 * tn + 4];
            u64 bp[4] = { b0.x, b0.y, b1.x, b1.y };
            u64 ad[4] = { dup2(a01.x), dup2(a01.y), dup2(a23.x), dup2(a23.y) };
#pragma unroll
            for (int p = 0; p < 4; p++)
#pragma unroll
                for (int q = 0; q < 4; q++)
                    fma2(acc[p][q], ad[p], bp[q]);
        }
        if (has_next) {
            int nb_ = cur ^ 1;
            *(float4*)&sA[nb_][kkA][mA] = make_float4(ra[0], ra[1], ra[2], ra[3]);
            sB[nb_][kkB][coB]     = rb[0];
            sB[nb_][kkB + 4][coB] = rb[1];
            __syncthreads();
        }
    }

    // ---- epilogue: unpack, bias + 2x2 maxpool (+ReLU/store split per path) ----
    float f[4][8];
#pragma unroll
    for (int p = 0; p < 4; p++)
#pragma unroll
        for (int q = 0; q < 4; q++)
            unpack2(acc[p][q], f[p][2 * q], f[p][2 * q + 1]);

    const float* bias = g_bias[set];
    if (!set) {
        int n = img / TT, t = img - n * TT;
        float* dst = &g_pooled[t][n][0][pr * OWW + tm];
#pragma unroll
        for (int j = 0; j < 8; j++) {
            int co = 8 * tn + j;
            float v = fmaxf(fmaxf(f[0][j], f[1][j]), fmaxf(f[2][j], f[3][j])) + bias[co];
            dst[(size_t)co * (OHH * OWW)] = v;
        }
    } else {
        int n = img - NIMG_SPK;
        float* dst = out + ANN_OFF + ((size_t)n * COUT * OHH + pr) * OWW + tm;
#pragma unroll
        for (int j = 0; j < 8; j++) {
            int co = 8 * tn + j;
            float v = fmaxf(fmaxf(f[0][j], f[1][j]), fmaxf(f[2][j], f[3][j])) + bias[co];
            dst[(size_t)co * (OHH * OWW)] = fmaxf(v, 0.f);
        }
    }
}

// ---------------------------------------------------------------------------
// Temporal LIF scan: each thread owns one (n, c, pixel) neuron, loops T=20.
// ---------------------------------------------------------------------------
__global__ void scan_kernel(float* __restrict__ out)
{
    int idx = blockIdx.x * blockDim.x + threadIdx.x;
    if (idx >= NB * COUT * OHH * OWW) return;
    int pix = idx & 1023;
    int c   = (idx >> 10) & 63;
    int n   = idx >> 16;

    const float* src = &g_pooled[0][n][c][pix];
    float* dspike = out + (((size_t)n * TT) * COUT + c) * 1024 + pix;

    float pot = 0.f, mask = 0.f, cnt = 0.f;
#pragma unroll
    for (int t = 0; t < TT; t++) {
        pot += src[(size_t)t * NB * COUT * 1024];
        float s = (pot >= 1.f) ? (1.f - mask) : 0.f;
        pot -= s;
        if (s != 0.f) mask = 1.f;
        cnt += s;
        dspike[(size_t)t * COUT * 1024] = s;
    }
    out[COUNT_OFF + (size_t)idx] = cnt;
}

// ---------------------------------------------------------------------------
extern "C" void kernel_launch(void* const* d_in, const int* in_sizes, int n_in,
                              void* d_out, int out_size)
{
    const float* x_st  = (const float*)d_in[0];  // (8,20,32,64,64)
    const float* x_sc  = (const float*)d_in[1];  // (8,32,64,64)
    const float* w     = (const float*)d_in[2];  // (64,32,3,3)
    const float* b     = (const float*)d_in[3];  // (64)
    const float* gamma = (const float*)d_in[4];
    const float* beta  = (const float*)d_in[5];
    const float* rm    = (const float*)d_in[6];
    const float* rv    = (const float*)d_in[7];
    float* out = (float*)d_out;
    (void)in_sizes; (void)n_in; (void)out_size;

    prep_kernel<<<(2 * KTOT * COUT + 255) / 256, 256>>>(w, b, gamma, beta, rm, rv);
    conv_pool_kernel<<<dim3(NIMG, OHH), 256>>>(x_st, x_sc, out);
    scan_kernel<<<(NB * COUT * OHH * OWW + 255) / 256, 256>>>(out);
}